// round 1
// baseline (speedup 1.0000x reference)
#include <cuda_runtime.h>
#include <math.h>

#define Tn 4096
#define Hn 2048
#define En 32
#define Fn 768
#define TOPK 4

// ---------------- scratch (device globals, no allocation) ----------------
__device__ int   g_topk_idx[Tn * TOPK];
__device__ float g_topk_w[Tn * TOPK];
__device__ int   g_counts[En];
__device__ int   g_offsets[En];
__device__ int   g_cursor[En];
__device__ int   g_tok[Tn * TOPK];    // token id, grouped by expert
__device__ float g_tokw[Tn * TOPK];   // routing weight, grouped by expert
__device__ float g_hdn[(size_t)Tn * TOPK * Fn];  // ~50 MB intermediate

// ---------------- zero output + counters ----------------
__global__ void zero_kernel(float* out) {
    int n = Tn * Hn;
    for (int i = blockIdx.x * blockDim.x + threadIdx.x; i < n;
         i += gridDim.x * blockDim.x)
        out[i] = 0.f;
    if (blockIdx.x == 0 && threadIdx.x < En) {
        g_counts[threadIdx.x] = 0;
        g_cursor[threadIdx.x] = 0;
    }
}

// ---------------- router: logits, softmax, top-4, renorm ----------------
__global__ __launch_bounds__(256) void router_kernel(
    const float* __restrict__ x, const float* __restrict__ gw,
    float* __restrict__ logits_out)  // may be nullptr
{
    int t = blockIdx.x;
    int tid = threadIdx.x;
    int warp = tid >> 5, lane = tid & 31;

    __shared__ float sx[Hn];
    __shared__ float slog[En];

    for (int i = tid; i < Hn; i += 256) sx[i] = x[(size_t)t * Hn + i];
    __syncthreads();

    // 8 warps, each does 4 experts; coalesced weight reads
    for (int e = warp; e < En; e += 8) {
        const float* w = gw + (size_t)e * Hn;
        float acc = 0.f;
        for (int k = lane; k < Hn; k += 32) acc += sx[k] * w[k];
        #pragma unroll
        for (int o = 16; o > 0; o >>= 1)
            acc += __shfl_xor_sync(0xffffffffu, acc, o);
        if (lane == 0) slog[e] = acc;
    }
    __syncthreads();

    if (warp == 0) {
        float l = slog[lane];
        if (logits_out) logits_out[(size_t)t * En + lane] = l;

        // softmax (warp-wide, E=32)
        float m = l;
        #pragma unroll
        for (int o = 16; o > 0; o >>= 1)
            m = fmaxf(m, __shfl_xor_sync(0xffffffffu, m, o));
        float p = __expf(l - m);
        float s = p;
        #pragma unroll
        for (int o = 16; o > 0; o >>= 1)
            s += __shfl_xor_sync(0xffffffffu, s, o);
        p /= s;

        // top-4 via 4 argmax passes
        float myp = p;
        float tw[TOPK]; int ti[TOPK];
        float wsum = 0.f;
        #pragma unroll
        for (int j = 0; j < TOPK; j++) {
            float v = myp; int idx = lane;
            #pragma unroll
            for (int o = 16; o > 0; o >>= 1) {
                float ov = __shfl_xor_sync(0xffffffffu, v, o);
                int   oi = __shfl_xor_sync(0xffffffffu, idx, o);
                if (ov > v || (ov == v && oi < idx)) { v = ov; idx = oi; }
            }
            tw[j] = v; ti[j] = idx; wsum += v;
            if (lane == idx) myp = -1.f;
        }
        if (lane < TOPK) {
            int e = ti[lane];
            g_topk_idx[t * TOPK + lane] = e;
            g_topk_w[t * TOPK + lane] = tw[lane] / wsum;
            atomicAdd(&g_counts[e], 1);
        }
    }
}

// ---------------- exclusive scan over 32 expert counts ----------------
__global__ void scan_kernel() {
    int lane = threadIdx.x;
    int c = g_counts[lane];
    int inc = c;
    #pragma unroll
    for (int o = 1; o < 32; o <<= 1) {
        int nv = __shfl_up_sync(0xffffffffu, inc, o);
        if (lane >= o) inc += nv;
    }
    g_offsets[lane] = inc - c;
}

// ---------------- scatter token assignments into per-expert groups ----
__global__ void scatter_kernel() {
    int i = blockIdx.x * blockDim.x + threadIdx.x;
    if (i >= Tn * TOPK) return;
    int e = g_topk_idx[i];
    int pos = atomicAdd(&g_cursor[e], 1);
    int slot = g_offsets[e] + pos;
    g_tok[slot]  = i >> 2;
    g_tokw[slot] = g_topk_w[i];
}

// ---------------- GEMM1: hdn = w * silu(x@wg) * (x@wu), grouped ---------
__global__ __launch_bounds__(256) void gemmA_kernel(
    const float* __restrict__ x,
    const float* __restrict__ wg, const float* __restrict__ wu)
{
    int e = blockIdx.z;
    int cnt = g_counts[e];
    int m0 = blockIdx.y * 64;
    if (m0 >= cnt) return;
    int base = g_offsets[e];
    int n0 = blockIdx.x * 64;

    __shared__ float As[16][64];
    __shared__ float Bg[16][64];
    __shared__ float Bu[16][64];

    int tid = threadIdx.x;
    int tx = tid & 15, ty = tid >> 4;

    int am = tid >> 2;
    int ak = (tid & 3) * 4;
    int arow = m0 + am;
    int tokA = (arow < cnt) ? g_tok[base + arow] : -1;

    int bk = tid >> 4;
    int bn = (tid & 15) * 4;
    const float* wgp = wg + (size_t)e * Hn * Fn;
    const float* wup = wu + (size_t)e * Hn * Fn;

    float accg[4][4] = {}, accu[4][4] = {};

    for (int k0 = 0; k0 < Hn; k0 += 16) {
        float4 av = make_float4(0.f, 0.f, 0.f, 0.f);
        if (tokA >= 0)
            av = *(const float4*)(x + (size_t)tokA * Hn + k0 + ak);
        As[ak + 0][am] = av.x; As[ak + 1][am] = av.y;
        As[ak + 2][am] = av.z; As[ak + 3][am] = av.w;

        *(float4*)&Bg[bk][bn] =
            *(const float4*)(wgp + (size_t)(k0 + bk) * Fn + n0 + bn);
        *(float4*)&Bu[bk][bn] =
            *(const float4*)(wup + (size_t)(k0 + bk) * Fn + n0 + bn);
        __syncthreads();

        #pragma unroll
        for (int k = 0; k < 16; k++) {
            float4 a = *(const float4*)&As[k][ty * 4];
            float4 g = *(const float4*)&Bg[k][tx * 4];
            float4 u = *(const float4*)&Bu[k][tx * 4];
            float aa[4] = {a.x, a.y, a.z, a.w};
            float gg[4] = {g.x, g.y, g.z, g.w};
            float uu[4] = {u.x, u.y, u.z, u.w};
            #pragma unroll
            for (int i = 0; i < 4; i++)
                #pragma unroll
                for (int j = 0; j < 4; j++) {
                    accg[i][j] = fmaf(aa[i], gg[j], accg[i][j]);
                    accu[i][j] = fmaf(aa[i], uu[j], accu[i][j]);
                }
        }
        __syncthreads();
    }

    #pragma unroll
    for (int i = 0; i < 4; i++) {
        int row = m0 + ty * 4 + i;
        if (row >= cnt) continue;
        int slot = base + row;
        float w = g_tokw[slot];
        float* hp = g_hdn + (size_t)slot * Fn + n0 + tx * 4;
        #pragma unroll
        for (int j = 0; j < 4; j++) {
            float gv = accg[i][j];
            float sil = gv / (1.f + __expf(-gv));
            hp[j] = w * sil * accu[i][j];
        }
    }
}

// ---------------- GEMM2: out += hdn @ wd, grouped, atomic accumulate ----
__global__ __launch_bounds__(256) void gemmB_kernel(
    const float* __restrict__ wd, float* __restrict__ out)
{
    int e = blockIdx.z;
    int cnt = g_counts[e];
    int m0 = blockIdx.y * 64;
    if (m0 >= cnt) return;
    int base = g_offsets[e];
    int n0 = blockIdx.x * 64;

    __shared__ float As[16][64];
    __shared__ float Bs[16][64];

    int tid = threadIdx.x;
    int tx = tid & 15, ty = tid >> 4;

    int am = tid >> 2;
    int ak = (tid & 3) * 4;
    int arow = m0 + am;
    bool avalid = arow < cnt;
    size_t aslot = avalid ? (size_t)(base + arow) : 0;

    int bk = tid >> 4;
    int bn = (tid & 15) * 4;
    const float* wdp = wd + (size_t)e * Fn * Hn;

    float acc[4][4] = {};

    for (int k0 = 0; k0 < Fn; k0 += 16) {
        float4 av = make_float4(0.f, 0.f, 0.f, 0.f);
        if (avalid)
            av = *(const float4*)(g_hdn + aslot * Fn + k0 + ak);
        As[ak + 0][am] = av.x; As[ak + 1][am] = av.y;
        As[ak + 2][am] = av.z; As[ak + 3][am] = av.w;

        *(float4*)&Bs[bk][bn] =
            *(const float4*)(wdp + (size_t)(k0 + bk) * Hn + n0 + bn);
        __syncthreads();

        #pragma unroll
        for (int k = 0; k < 16; k++) {
            float4 a = *(const float4*)&As[k][ty * 4];
            float4 b = *(const float4*)&Bs[k][tx * 4];
            float aa[4] = {a.x, a.y, a.z, a.w};
            float bb[4] = {b.x, b.y, b.z, b.w};
            #pragma unroll
            for (int i = 0; i < 4; i++)
                #pragma unroll
                for (int j = 0; j < 4; j++)
                    acc[i][j] = fmaf(aa[i], bb[j], acc[i][j]);
        }
        __syncthreads();
    }

    #pragma unroll
    for (int i = 0; i < 4; i++) {
        int row = m0 + ty * 4 + i;
        if (row >= cnt) continue;
        int t = g_tok[base + row];
        float* op = out + (size_t)t * Hn + n0 + tx * 4;
        #pragma unroll
        for (int j = 0; j < 4; j++)
            atomicAdd(&op[j], acc[i][j]);
    }
}

// ---------------- launcher ----------------
extern "C" void kernel_launch(void* const* d_in, const int* in_sizes, int n_in,
                              void* d_out, int out_size) {
    const float* x  = (const float*)d_in[0];  // hidden_states [2,2048,2048]
    const float* gw = (const float*)d_in[1];  // gate_w [32,2048]
    const float* wg = (const float*)d_in[2];  // w_gate [32,2048,768]
    const float* wu = (const float*)d_in[3];  // w_up   [32,2048,768]
    const float* wd = (const float*)d_in[4];  // w_down [32,768,2048]
    float* out = (float*)d_out;

    // router logits go right after the main output if the buffer has room
    float* logits_out = nullptr;
    if (out_size >= Tn * Hn + Tn * En) logits_out = out + (size_t)Tn * Hn;

    zero_kernel<<<1024, 256>>>(out);
    router_kernel<<<Tn, 256>>>(x, gw, logits_out);
    scan_kernel<<<1, 32>>>();
    scatter_kernel<<<(Tn * TOPK + 255) / 256, 256>>>();
    gemmA_kernel<<<dim3(Fn / 64, Tn / 64, En), 256>>>(x, wg, wu);
    gemmB_kernel<<<dim3(Hn / 64, Tn / 64, En), 256>>>(wd, out);
}